// round 2
// baseline (speedup 1.0000x reference)
#include <cuda_runtime.h>
#include <cstdint>

// MeanAggregator: out[b, :] = (1/S) * sum_s features[neigh_idx[b, s], :]
// features: [N_NODES=1e6, D=128] fp32; neigh_idx: [B=100000, S=10] (int32 —
// JAX x32 mode silently downgrades the requested int64); out: [B, 128] fp32
//
// One warp per output row b. Each lane owns 4 consecutive floats (float4),
// so one warp load of a feature row = 32 lanes x 16B = 512B, fully coalesced.
// All 10 indices are loaded first, then all 10 row-loads are issued
// back-to-back (MLP ~= 10) before the accumulate, hiding DRAM latency.

#define D_FEAT 128
#define NUM_SAMPLE 10
#define N_NODES 1000000

__global__ __launch_bounds__(256) void mean_agg_kernel(
    const float* __restrict__ features,
    const int* __restrict__ neigh_idx,
    float* __restrict__ out,
    int batch)
{
    const int warp_id = (blockIdx.x * blockDim.x + threadIdx.x) >> 5;
    const int lane    = threadIdx.x & 31;
    if (warp_id >= batch) return;

    // Load all 10 indices (uniform across warp -> broadcast loads).
    const int* ip = neigh_idx + (size_t)warp_id * NUM_SAMPLE;
    int idx[NUM_SAMPLE];
#pragma unroll
    for (int s = 0; s < NUM_SAMPLE; s++) {
        int v = __ldg(ip + s);
        // Defensive clamp: if the dtype assumption is ever wrong we want a
        // finite rel_err diagnostic, not an illegal-access fault.
        idx[s] = min(max(v, 0), N_NODES - 1);
    }

    // Issue all 10 gathers back-to-back for maximum MLP.
    float4 v[NUM_SAMPLE];
#pragma unroll
    for (int s = 0; s < NUM_SAMPLE; s++) {
        const float4* row = reinterpret_cast<const float4*>(
            features + (size_t)idx[s] * D_FEAT);
        v[s] = __ldg(row + lane);
    }

    float4 acc;
    acc.x = v[0].x; acc.y = v[0].y; acc.z = v[0].z; acc.w = v[0].w;
#pragma unroll
    for (int s = 1; s < NUM_SAMPLE; s++) {
        acc.x += v[s].x;
        acc.y += v[s].y;
        acc.z += v[s].z;
        acc.w += v[s].w;
    }

    const float inv = 1.0f / (float)NUM_SAMPLE;
    acc.x *= inv; acc.y *= inv; acc.z *= inv; acc.w *= inv;

    float4* orow = reinterpret_cast<float4*>(out + (size_t)warp_id * D_FEAT);
    orow[lane] = acc;
}

extern "C" void kernel_launch(void* const* d_in, const int* in_sizes, int n_in,
                              void* d_out, int out_size) {
    const float* features  = (const float*)d_in[0];
    const int*   neigh_idx = (const int*)d_in[1];
    float*       out       = (float*)d_out;

    const int batch = in_sizes[1] / NUM_SAMPLE;  // 100000

    const int threads = 256;                     // 8 warps/block
    const int warps_per_block = threads / 32;
    const int blocks = (batch + warps_per_block - 1) / warps_per_block;

    mean_agg_kernel<<<blocks, threads>>>(features, neigh_idx, out, batch);
}

// round 4
// speedup vs baseline: 1.0222x; 1.0222x over previous
#include <cuda_runtime.h>
#include <cstdint>

// MeanAggregator: out[b, :] = (1/S) * sum_s features[neigh_idx[b, s], :]
// features: [1e6, 128] fp32; neigh_idx: [100000, 10] int32; out: [100000, 128] fp32
//
// One warp per output row b; lane owns one float4 (512B/row fully coalesced).
// All 10 row gathers issued back-to-back (MLP~=10/lane).
// R4: L2 policy via createpolicy + ld.global.nc.L2::cache_hint (ptxas rejects
// the literal evict_last modifier on .v4.f32); output stores streaming (st.cs).

#define D_FEAT 128
#define NUM_SAMPLE 10
#define N_NODES 1000000

__device__ __forceinline__ uint64_t make_evict_last_policy() {
    uint64_t pol;
    asm("createpolicy.fractional.L2::evict_last.b64 %0, 1.0;" : "=l"(pol));
    return pol;
}

__device__ __forceinline__ float4 ldg_hint(const float4* p, uint64_t pol) {
    float4 r;
    asm volatile("ld.global.nc.L2::cache_hint.v4.f32 {%0,%1,%2,%3}, [%4], %5;"
                 : "=f"(r.x), "=f"(r.y), "=f"(r.z), "=f"(r.w)
                 : "l"(p), "l"(pol));
    return r;
}

__device__ __forceinline__ void stg_streaming(float4* p, float4 v) {
    asm volatile("st.global.cs.v4.f32 [%0], {%1,%2,%3,%4};"
                 :: "l"(p), "f"(v.x), "f"(v.y), "f"(v.z), "f"(v.w)
                 : "memory");
}

__global__ __launch_bounds__(256) void mean_agg_kernel(
    const float* __restrict__ features,
    const int* __restrict__ neigh_idx,
    float* __restrict__ out,
    int batch)
{
    const int warp_id = (blockIdx.x * blockDim.x + threadIdx.x) >> 5;
    const int lane    = threadIdx.x & 31;
    if (warp_id >= batch) return;

    const uint64_t pol = make_evict_last_policy();

    // Load all 10 indices (uniform across warp -> broadcast loads).
    const int* ip = neigh_idx + (size_t)warp_id * NUM_SAMPLE;
    int idx[NUM_SAMPLE];
#pragma unroll
    for (int s = 0; s < NUM_SAMPLE; s++) {
        int v = __ldg(ip + s);
        idx[s] = min(max(v, 0), N_NODES - 1);
    }

    // Issue all 10 gathers back-to-back for maximum MLP.
    float4 v[NUM_SAMPLE];
#pragma unroll
    for (int s = 0; s < NUM_SAMPLE; s++) {
        const float4* row = reinterpret_cast<const float4*>(
            features + (size_t)idx[s] * D_FEAT);
        v[s] = ldg_hint(row + lane, pol);
    }

    float4 acc;
    acc.x = v[0].x; acc.y = v[0].y; acc.z = v[0].z; acc.w = v[0].w;
#pragma unroll
    for (int s = 1; s < NUM_SAMPLE; s++) {
        acc.x += v[s].x;
        acc.y += v[s].y;
        acc.z += v[s].z;
        acc.w += v[s].w;
    }

    const float inv = 1.0f / (float)NUM_SAMPLE;
    acc.x *= inv; acc.y *= inv; acc.z *= inv; acc.w *= inv;

    float4* orow = reinterpret_cast<float4*>(out + (size_t)warp_id * D_FEAT);
    stg_streaming(orow + lane, acc);
}

extern "C" void kernel_launch(void* const* d_in, const int* in_sizes, int n_in,
                              void* d_out, int out_size) {
    const float* features  = (const float*)d_in[0];
    const int*   neigh_idx = (const int*)d_in[1];
    float*       out       = (float*)d_out;

    const int batch = in_sizes[1] / NUM_SAMPLE;  // 100000

    const int threads = 256;                     // 8 warps/block
    const int warps_per_block = threads / 32;
    const int blocks = (batch + warps_per_block - 1) / warps_per_block;

    mean_agg_kernel<<<blocks, threads>>>(features, neigh_idx, out, batch);
}